// round 11
// baseline (speedup 1.0000x reference)
#include <cuda_runtime.h>
#include <cuda_bf16.h>
#include <math.h>

// Problem dims
#define Bb  64
#define Ss  512
#define Ee  256
#define Hh  512
#define Tt  9
#define G4H 2048   // 4*H

// ---------------------------------------------------------------------------
// Scratch (device globals; no runtime allocation allowed)
// ---------------------------------------------------------------------------
__device__ float g_xw[2][(size_t)Bb * Ss * G4H];      // input projections per dir (536 MB)
__device__ float g_hseq[2][(size_t)Bb * Ss * Hh];     // h history per dir (134 MB)
__device__ float g_hstate[2][2][Bb * Hh];             // [dir][parity][B*H]
__device__ float g_cstate[2][Bb * Hh];                // [dir][B*H]
__device__ float g_pots[(size_t)Bb * Ss * Tt];
__device__ float g_dec_dummy[Bb * Ss];

// ---------------------------------------------------------------------------
// f32x2 helpers (packed fp32 FMA: 2x scalar FFMA throughput on sm_103a)
// ---------------------------------------------------------------------------
__device__ __forceinline__ void fma2(unsigned long long& d, unsigned long long a,
                                     unsigned long long b) {
    asm("fma.rn.f32x2 %0, %1, %2, %0;" : "+l"(d) : "l"(a), "l"(b));
}
__device__ __forceinline__ unsigned long long bcast2(float x) {
    unsigned long long r;
    asm("mov.b64 %0, {%1, %1};" : "=l"(r) : "r"(__float_as_uint(x)));
    return r;
}
__device__ __forceinline__ float2 unpack2(unsigned long long v) {
    float2 f;
    asm("mov.b64 {%0, %1}, %2;" : "=f"(f.x), "=f"(f.y) : "l"(v));
    return f;
}

__device__ __forceinline__ float sigf(float x) { return 1.0f / (1.0f + expf(-x)); }

// ---------------------------------------------------------------------------
// Zero the recurrent state
// ---------------------------------------------------------------------------
__global__ void k_zero_state() {
    int i = blockIdx.x * 256 + threadIdx.x;
    if (i < Bb * Hh) {
        g_hstate[0][0][i] = 0.f; g_hstate[0][1][i] = 0.f;
        g_hstate[1][0][i] = 0.f; g_hstate[1][1][i] = 0.f;
        g_cstate[0][i] = 0.f;    g_cstate[1][i] = 0.f;
    }
}

// ---------------------------------------------------------------------------
// Embedding + input projection: xw[dir][b,s,:] = emb[inputs[b,s]] @ W_dir + b_dir
// GEMM: M=32768 (b*s), K=256, N=2048. Tile 64x64, BK=16, 256 threads,
// 2 rows x 8 cols per thread via f32x2 (col pairs packed).
// ---------------------------------------------------------------------------
__global__ void __launch_bounds__(256) k_input_gemm(
    const int* __restrict__ inputs, const float* __restrict__ emb,
    const float* __restrict__ W_fw, const float* __restrict__ b_fw,
    const float* __restrict__ W_bw, const float* __restrict__ b_bw)
{
    const int dir = blockIdx.z;
    const float* __restrict__ W    = dir ? W_bw : W_fw;
    const float* __restrict__ bias = dir ? b_bw : b_fw;
    float* __restrict__ out = g_xw[dir];

    const int m0 = blockIdx.y * 64;
    const int n0 = blockIdx.x * 64;

    __shared__ __align__(16) float As[16][65];  // [kk][m], padded
    __shared__ __align__(16) float Bs[16][64];  // [kk][n]
    __shared__ int ridx[64];

    const int t = threadIdx.x;
    if (t < 64) ridx[t] = inputs[m0 + t];
    __syncthreads();

    const int tx = t & 7;        // col group (8 cols)
    const int ty = t >> 3;       // row pair (0..31)
    const int r0 = ty * 2;
    const int c0 = tx * 8;

    unsigned long long acc[2][4];
#pragma unroll
    for (int r = 0; r < 2; r++)
#pragma unroll
        for (int c = 0; c < 4; c++) acc[r][c] = 0ULL;

    for (int k0 = 0; k0 < Ee; k0 += 16) {
#pragma unroll
        for (int i = 0; i < 4; i++) {
            int li = t + i * 256;
            int m = li >> 4, kk = li & 15;
            As[kk][m] = emb[(size_t)ridx[m] * Ee + k0 + kk];
        }
#pragma unroll
        for (int i = 0; i < 4; i++) {
            int li = t + i * 256;
            int kk = li >> 6, n = li & 63;
            Bs[kk][n] = W[(size_t)(k0 + kk) * G4H + n0 + n];
        }
        __syncthreads();
#pragma unroll
        for (int kk = 0; kk < 16; kk++) {
            unsigned long long a0 = bcast2(As[kk][r0]);
            unsigned long long a1 = bcast2(As[kk][r0 + 1]);
#pragma unroll
            for (int c = 0; c < 4; c++) {
                unsigned long long u2 = *(const unsigned long long*)&Bs[kk][c0 + 2 * c];
                fma2(acc[0][c], a0, u2);
                fma2(acc[1][c], a1, u2);
            }
        }
        __syncthreads();
    }

#pragma unroll
    for (int r = 0; r < 2; r++) {
        int m = m0 + r0 + r;
#pragma unroll
        for (int c = 0; c < 4; c++) {
            float2 v = unpack2(acc[r][c]);
            int n = n0 + c0 + 2 * c;
            v.x += bias[n];
            v.y += bias[n + 1];
            *(float2*)&out[(size_t)m * G4H + n] = v;
        }
    }
}

// ---------------------------------------------------------------------------
// One LSTM time step, both directions.
// grid = (H/8, 2): 128 blocks, 128 threads.
// Block (dir, j0=bx*8) computes z[b][gate][j0..j0+7] for all b (tile 64x32,
// K=512, BK=32, double-buffered smem), then applies gates for its 8 hidden
// units per row, updating c (in place) and h (double-buffered by step parity).
// ---------------------------------------------------------------------------
__global__ void __launch_bounds__(128) k_lstm_step(
    const float* __restrict__ U_fw, const float* __restrict__ U_bw, int step)
{
    const int dir = blockIdx.y;
    const float* __restrict__ U = dir ? U_bw : U_fw;
    const int j0 = blockIdx.x * 8;
    const int s = dir ? (Ss - 1 - step) : step;

    const float* __restrict__ hin  = g_hstate[dir][step & 1];
    float* __restrict__ hout       = g_hstate[dir][(step & 1) ^ 1];
    float* __restrict__ cst        = g_cstate[dir];
    const float* __restrict__ xw   = g_xw[dir];
    float* __restrict__ hseq       = g_hseq[dir];

    __shared__ __align__(16) float As[2][32][65];  // [buf][kk][b], padded
    __shared__ __align__(16) float Us[2][32][32];  // [buf][kk][c], c = gate*8+jj

    const int t   = threadIdx.x;
    const int jp  = t & 3;        // jj pair: jj2 = 2*jp
    const int ty  = t >> 2;       // rows 2ty, 2ty+1
    const int jj2 = jp * 2;

    // loader lane mapping
    const int kkA = t & 31;       // A: kk
    const int bA0 = t >> 5;       // A: base row
    const int cU  = t & 31;       // U: local column
    const int kU0 = t >> 5;       // U: base kk
    const int gcol = ((cU >> 3) * Hh) + j0 + (cU & 7); // global U column

    unsigned long long acc[2][4];
#pragma unroll
    for (int r = 0; r < 2; r++)
#pragma unroll
        for (int g = 0; g < 4; g++) acc[r][g] = 0ULL;

    float ra[16], ru[8];
    // prefetch chunk 0
#pragma unroll
    for (int i = 0; i < 16; i++) ra[i] = hin[(bA0 + 4 * i) * Hh + kkA];
#pragma unroll
    for (int i = 0; i < 8; i++)  ru[i] = U[(size_t)(kU0 + 4 * i) * G4H + gcol];

    int buf = 0;
#pragma unroll 1
    for (int ch = 0; ch < 16; ch++) {
        // stage current chunk into smem
#pragma unroll
        for (int i = 0; i < 16; i++) As[buf][kkA][bA0 + 4 * i] = ra[i];
#pragma unroll
        for (int i = 0; i < 8; i++)  Us[buf][kU0 + 4 * i][cU] = ru[i];
        __syncthreads();
        // prefetch next chunk (overlaps with compute below)
        if (ch < 15) {
            int k0n = (ch + 1) * 32;
#pragma unroll
            for (int i = 0; i < 16; i++)
                ra[i] = hin[(bA0 + 4 * i) * Hh + k0n + kkA];
#pragma unroll
            for (int i = 0; i < 8; i++)
                ru[i] = U[(size_t)(k0n + kU0 + 4 * i) * G4H + gcol];
        }
#pragma unroll
        for (int kk = 0; kk < 32; kk++) {
            unsigned long long a0 = bcast2(As[buf][kk][2 * ty]);
            unsigned long long a1 = bcast2(As[buf][kk][2 * ty + 1]);
#pragma unroll
            for (int g = 0; g < 4; g++) {
                unsigned long long u2 =
                    *(const unsigned long long*)&Us[buf][kk][g * 8 + jj2];
                fma2(acc[0][g], a0, u2);
                fma2(acc[1][g], a1, u2);
            }
        }
        __syncthreads();
        buf ^= 1;
    }

    // epilogue: gates (Keras order i,f,g,o)
#pragma unroll
    for (int r = 0; r < 2; r++) {
        const int b = 2 * ty + r;
        float2 zi = unpack2(acc[r][0]);
        float2 zf = unpack2(acc[r][1]);
        float2 zg = unpack2(acc[r][2]);
        float2 zo = unpack2(acc[r][3]);
        const size_t xbase = ((size_t)b * Ss + s) * G4H;
#pragma unroll
        for (int q = 0; q < 2; q++) {
            const int jj = jj2 + q;
            const int j  = j0 + jj;
            float vi = (q ? zi.y : zi.x) + xw[xbase + 0 * Hh + j];
            float vf = (q ? zf.y : zf.x) + xw[xbase + 1 * Hh + j];
            float vg = (q ? zg.y : zg.x) + xw[xbase + 2 * Hh + j];
            float vo = (q ? zo.y : zo.x) + xw[xbase + 3 * Hh + j];
            float c_old = cst[b * Hh + j];
            float cn = sigf(vf) * c_old + sigf(vi) * tanhf(vg);
            float hn = sigf(vo) * tanhf(cn);
            cst[b * Hh + j]  = cn;
            hout[b * Hh + j] = hn;
            hseq[((size_t)b * Ss + s) * Hh + j] = hn;
        }
    }
}

// ---------------------------------------------------------------------------
// Dense + CRF potentials: logits = [h_fw|h_bw] @ Wd + bd ; pots = logits @ crf_W
// + crf_b (+ boundary biases). One block per (b,s); 9 warps (one per tag).
// ---------------------------------------------------------------------------
__global__ void __launch_bounds__(288) k_dense_crf(
    const float* __restrict__ Wd, const float* __restrict__ bd,
    const float* __restrict__ crf_W, const float* __restrict__ crf_b,
    const float* __restrict__ left_b, const float* __restrict__ right_b)
{
    const int bs = blockIdx.x;          // 0..B*S-1
    const int s  = bs & (Ss - 1);

    __shared__ float hsm[2 * Hh];
    __shared__ float lg[Tt];

    const int t = threadIdx.x;
    for (int i = t; i < Hh; i += 288) hsm[i]      = g_hseq[0][(size_t)bs * Hh + i];
    for (int i = t; i < Hh; i += 288) hsm[Hh + i] = g_hseq[1][(size_t)bs * Hh + i];
    __syncthreads();

    const int w = t >> 5, lane = t & 31;
    if (w < Tt) {
        float sum = 0.f;
        for (int k = lane; k < 2 * Hh; k += 32)
            sum += hsm[k] * Wd[k * Tt + w];
#pragma unroll
        for (int off = 16; off; off >>= 1)
            sum += __shfl_xor_sync(0xffffffffu, sum, off);
        if (lane == 0) lg[w] = sum + bd[w];
    }
    __syncthreads();
    if (t < Tt) {
        float p = crf_b[t];
#pragma unroll
        for (int k = 0; k < Tt; k++) p += lg[k] * crf_W[k * Tt + t];
        if (s == 0)      p += left_b[t];
        if (s == Ss - 1) p += right_b[t];
        g_pots[(size_t)bs * Tt + t] = p;
    }
}

// ---------------------------------------------------------------------------
// Viterbi decode. One block per batch element, 32 threads (lanes 0..8 active).
// argmax tie-break = first index (matches jnp.argmax).
// ---------------------------------------------------------------------------
__global__ void k_viterbi(const float* __restrict__ trans, float* dec, int as_int)
{
    const int b = blockIdx.x;
    const int t = threadIdx.x;
    if (dec == nullptr) dec = g_dec_dummy;

    __shared__ float alpha[Tt];
    __shared__ float nalpha[Tt];
    __shared__ float tr[Tt * Tt];
    __shared__ short bp[Ss - 1][Tt];

    for (int i = t; i < Tt * Tt; i += 32) tr[i] = trans[i];
    if (t < Tt) alpha[t] = g_pots[((size_t)b * Ss) * Tt + t];
    __syncwarp();

    for (int s = 1; s < Ss; s++) {
        if (t < Tt) {
            float best = alpha[0] + tr[t];
            int arg = 0;
#pragma unroll
            for (int p = 1; p < Tt; p++) {
                float sc = alpha[p] + tr[p * Tt + t];
                if (sc > best) { best = sc; arg = p; }
            }
            nalpha[t] = best + g_pots[((size_t)b * Ss + s) * Tt + t];
            bp[s - 1][t] = (short)arg;
        }
        __syncwarp();
        if (t < Tt) alpha[t] = nalpha[t];
        __syncwarp();
    }

    if (t == 0) {
        int tag = 0; float best = alpha[0];
#pragma unroll
        for (int p = 1; p < Tt; p++)
            if (alpha[p] > best) { best = alpha[p]; tag = p; }
        if (as_int) ((int*)dec)[(size_t)b * Ss + Ss - 1] = tag;
        else        dec[(size_t)b * Ss + Ss - 1] = (float)tag;
        for (int s = Ss - 2; s >= 0; s--) {
            tag = bp[s][tag];
            if (as_int) ((int*)dec)[(size_t)b * Ss + s] = tag;
            else        dec[(size_t)b * Ss + s] = (float)tag;
        }
    }
}

__global__ void k_copy_pots(float* __restrict__ dst) {
    int i = blockIdx.x * 256 + threadIdx.x;
    if (i < Bb * Ss * Tt) dst[i] = g_pots[i];
}

// ---------------------------------------------------------------------------
// Launch
// ---------------------------------------------------------------------------
extern "C" void kernel_launch(void* const* d_in, const int* in_sizes, int n_in,
                              void* d_out, int out_size)
{
    const int*   inputs = (const int*)  d_in[0];
    const float* emb    = (const float*)d_in[1];
    const float* W_fw   = (const float*)d_in[2];
    const float* U_fw   = (const float*)d_in[3];
    const float* b_fw   = (const float*)d_in[4];
    const float* W_bw   = (const float*)d_in[5];
    const float* U_bw   = (const float*)d_in[6];
    const float* b_bw   = (const float*)d_in[7];
    const float* Wd     = (const float*)d_in[8];
    const float* bd     = (const float*)d_in[9];
    const float* crf_W  = (const float*)d_in[10];
    const float* crf_b  = (const float*)d_in[11];
    const float* trans  = (const float*)d_in[12];
    const float* left_b = (const float*)d_in[13];
    const float* right_b= (const float*)d_in[14];

    float* out = (float*)d_out;
    const long long NDEC = (long long)Bb * Ss;        // 32768
    const long long NPOT = (long long)Bb * Ss * Tt;   // 294912

    float* dec_dst = nullptr;
    float* pot_dst = nullptr;
    int as_int = 0;
    if ((long long)out_size >= NDEC + NPOT) {
        dec_dst = out;            // decoded first, then pots (tuple order)
        pot_dst = out + NDEC;
    } else if ((long long)out_size == NPOT) {
        pot_dst = out;            // pots only
    } else {
        dec_dst = out;            // decoded only — likely int dtype
        as_int = 1;
    }

    k_zero_state<<<(Bb * Hh + 255) / 256, 256>>>();

    dim3 g1(G4H / 64, (Bb * Ss) / 64, 2);  // (32, 512, 2)
    k_input_gemm<<<g1, 256>>>(inputs, emb, W_fw, b_fw, W_bw, b_bw);

    dim3 g2(Hh / 8, 2);                     // 128 blocks
    for (int step = 0; step < Ss; step++)
        k_lstm_step<<<g2, 128>>>(U_fw, U_bw, step);

    k_dense_crf<<<Bb * Ss, 288>>>(Wd, bd, crf_W, crf_b, left_b, right_b);

    k_viterbi<<<Bb, 32>>>(trans, dec_dst, as_int);

    if (pot_dst)
        k_copy_pots<<<(Bb * Ss * Tt + 255) / 256, 256>>>(pot_dst);
}

// round 12
// speedup vs baseline: 1.8125x; 1.8125x over previous
#include <cuda_runtime.h>
#include <cuda_bf16.h>
#include <math.h>

// Problem dims
#define Bb  64
#define Ss  512
#define Ee  256
#define Hh  512
#define Tt  9
#define G4H 2048   // 4*H

#define PADU 34    // U smem row pad (floats)
#define PADH 68    // h smem row pad (floats, 16B-aligned rows)
#define NBJ  64    // j-blocks per direction

// ---------------------------------------------------------------------------
// Scratch (device globals; no runtime allocation allowed)
// ---------------------------------------------------------------------------
__device__ float g_xw[2][(size_t)Bb * Ss * G4H];      // input projections per dir
__device__ float g_hseq[2][(size_t)Bb * Ss * Hh];     // h history per dir [b][s][h]
__device__ float g_hstate[2][2][Hh * Bb];             // [dir][parity][j*64 + b]  (transposed!)
__device__ float g_pots[(size_t)Bb * Ss * Tt];
__device__ float g_dec_dummy[Bb * Ss];
__device__ unsigned g_cnt[2];                          // per-dir barrier counters

// ---------------------------------------------------------------------------
// f32x2 helpers
// ---------------------------------------------------------------------------
__device__ __forceinline__ void fma2(unsigned long long& d, unsigned long long a,
                                     unsigned long long b) {
    asm("fma.rn.f32x2 %0, %1, %2, %0;" : "+l"(d) : "l"(a), "l"(b));
}
__device__ __forceinline__ unsigned long long bcast2(float x) {
    unsigned long long r;
    asm("mov.b64 %0, {%1, %1};" : "=l"(r) : "r"(__float_as_uint(x)));
    return r;
}
__device__ __forceinline__ float2 unpack2(unsigned long long v) {
    float2 f;
    asm("mov.b64 {%0, %1}, %2;" : "=f"(f.x), "=f"(f.y) : "l"(v));
    return f;
}
__device__ __forceinline__ float sigf(float x) { return 1.0f / (1.0f + expf(-x)); }

// ---------------------------------------------------------------------------
// Zero state + barrier counters
// ---------------------------------------------------------------------------
__global__ void k_zero_state() {
    int i = blockIdx.x * 256 + threadIdx.x;
    if (i < Hh * Bb) {
        g_hstate[0][0][i] = 0.f; g_hstate[0][1][i] = 0.f;
        g_hstate[1][0][i] = 0.f; g_hstate[1][1][i] = 0.f;
    }
    if (i < 2) g_cnt[i] = 0u;
}

// ---------------------------------------------------------------------------
// Embedding + input projection (unchanged from R11): xw = emb[inputs] @ W + b
// ---------------------------------------------------------------------------
__global__ void __launch_bounds__(256) k_input_gemm(
    const int* __restrict__ inputs, const float* __restrict__ emb,
    const float* __restrict__ W_fw, const float* __restrict__ b_fw,
    const float* __restrict__ W_bw, const float* __restrict__ b_bw)
{
    const int dir = blockIdx.z;
    const float* __restrict__ W    = dir ? W_bw : W_fw;
    const float* __restrict__ bias = dir ? b_bw : b_fw;
    float* __restrict__ out = g_xw[dir];

    const int m0 = blockIdx.y * 64;
    const int n0 = blockIdx.x * 64;

    __shared__ __align__(16) float As[16][65];
    __shared__ __align__(16) float Bs[16][64];
    __shared__ int ridx[64];

    const int t = threadIdx.x;
    if (t < 64) ridx[t] = inputs[m0 + t];
    __syncthreads();

    const int tx = t & 7;
    const int ty = t >> 3;
    const int r0 = ty * 2;
    const int c0 = tx * 8;

    unsigned long long acc[2][4];
#pragma unroll
    for (int r = 0; r < 2; r++)
#pragma unroll
        for (int c = 0; c < 4; c++) acc[r][c] = 0ULL;

    for (int k0 = 0; k0 < Ee; k0 += 16) {
#pragma unroll
        for (int i = 0; i < 4; i++) {
            int li = t + i * 256;
            int m = li >> 4, kk = li & 15;
            As[kk][m] = emb[(size_t)ridx[m] * Ee + k0 + kk];
        }
#pragma unroll
        for (int i = 0; i < 4; i++) {
            int li = t + i * 256;
            int kk = li >> 6, n = li & 63;
            Bs[kk][n] = W[(size_t)(k0 + kk) * G4H + n0 + n];
        }
        __syncthreads();
#pragma unroll
        for (int kk = 0; kk < 16; kk++) {
            unsigned long long a0 = bcast2(As[kk][r0]);
            unsigned long long a1 = bcast2(As[kk][r0 + 1]);
#pragma unroll
            for (int c = 0; c < 4; c++) {
                unsigned long long u2 = *(const unsigned long long*)&Bs[kk][c0 + 2 * c];
                fma2(acc[0][c], a0, u2);
                fma2(acc[1][c], a1, u2);
            }
        }
        __syncthreads();
    }

#pragma unroll
    for (int r = 0; r < 2; r++) {
        int m = m0 + r0 + r;
#pragma unroll
        for (int c = 0; c < 4; c++) {
            float2 v = unpack2(acc[r][c]);
            int n = n0 + c0 + 2 * c;
            v.x += bias[n];
            v.y += bias[n + 1];
            *(float2*)&out[(size_t)m * G4H + n] = v;
        }
    }
}

// ---------------------------------------------------------------------------
// Persistent BiLSTM recurrence. grid=(64,2), 256 threads, all blocks resident.
// Block (dir, jb) owns z columns {gate*512 + jb*8 + jj} and keeps its U slice
// [512][32] in smem for all 512 steps. Software grid barrier per direction.
// h state global layout transposed: hstate[j*64 + b].
// ---------------------------------------------------------------------------
__global__ void __launch_bounds__(256) k_lstm_persistent(
    const float* __restrict__ U_fw, const float* __restrict__ U_bw)
{
    const int dir = blockIdx.y;
    const int jb  = blockIdx.x;
    const int j0  = jb * 8;
    const int tid = threadIdx.x;
    const float* __restrict__ U = dir ? U_bw : U_fw;

    extern __shared__ float sm[];
    float* Us = sm;                       // [512][PADU]
    float* Hs = sm + 512 * PADU;          // [2][64][PADH]
    float* Z0 = Hs;                       // [64][33]  (reuses Hs buf0 between steps)
    float* Z1 = Hs + 64 * 33;

    // ---- stage U slice once: Us[k][c], c = gate*8 + jj ----
    {
        const int c = tid & 31;
        const int gcol = (c >> 3) * Hh + j0 + (c & 7);
        const int kb = tid >> 5;
        for (int i = 0; i < 64; i++) {
            int k = kb + 8 * i;
            Us[k * PADU + c] = U[(size_t)k * G4H + gcol];
        }
    }

    // compute mapping: K-split halves, 4 rows x 4 cols per thread
    const int ks = tid >> 7;              // 0/1
    const int t7 = tid & 127;
    const int r0 = (t7 >> 3) * 4;         // batch rows r0..r0+3
    const int c0 = (t7 & 7) * 4;          // cols c0..c0+3

    // staging mapping
    const int skk = tid >> 4;             // 0..15
    const int sb  = (tid & 15) * 4;       // 0..60

    float c_reg[2] = {0.f, 0.f};
    float* __restrict__ hseq = g_hseq[dir];
    const float* __restrict__ xw = g_xw[dir];

    __syncthreads();

#pragma unroll 1
    for (int step = 0; step < Ss; step++) {
        const int s = dir ? (Ss - 1 - step) : step;
        const float* __restrict__ hin = g_hstate[dir][step & 1];
        float* __restrict__ hout      = g_hstate[dir][(step & 1) ^ 1];

        // prefetch gate biases from xw (used only in epilogue)
        float xwv[2][4];
#pragma unroll
        for (int q = 0; q < 2; q++) {
            int e = tid + q * 256;
            int b = e >> 3, jj = e & 7;
            const float* p = &xw[((size_t)b * Ss + s) * G4H + j0 + jj];
#pragma unroll
            for (int g = 0; g < 4; g++) xwv[q][g] = __ldcs(p + g * Hh);
        }

        unsigned long long acc[4][2];
#pragma unroll
        for (int r = 0; r < 4; r++) { acc[r][0] = 0ULL; acc[r][1] = 0ULL; }

        // prefetch chunk 0 of h (L2-coherent loads; L1 would be stale)
        float4 hv[4];
#pragma unroll
        for (int i = 0; i < 4; i++)
            hv[i] = __ldcg((const float4*)&hin[(skk + 16 * i) * 64 + sb]);

        int buf = 0;
#pragma unroll 1
        for (int ch = 0; ch < 8; ch++) {
            float* hb = Hs + buf * (64 * PADH);
#pragma unroll
            for (int i = 0; i < 4; i++)
                *(float4*)&hb[(skk + 16 * i) * PADH + sb] = hv[i];
            __syncthreads();
            if (ch < 7) {
                int k0n = (ch + 1) * 64;
#pragma unroll
                for (int i = 0; i < 4; i++)
                    hv[i] = __ldcg((const float4*)&hin[(k0n + skk + 16 * i) * 64 + sb]);
            }
            const float* ub  = Us + (ch * 64 + ks * 32) * PADU;
            const float* hbk = hb + (ks * 32) * PADH;
#pragma unroll 16
            for (int kk = 0; kk < 32; kk++) {
                float2 a01 = *(const float2*)&hbk[kk * PADH + r0];
                float2 a23 = *(const float2*)&hbk[kk * PADH + r0 + 2];
                unsigned long long u01 = *(const unsigned long long*)&ub[kk * PADU + c0];
                unsigned long long u23 = *(const unsigned long long*)&ub[kk * PADU + c0 + 2];
                unsigned long long A;
                A = bcast2(a01.x); fma2(acc[0][0], A, u01); fma2(acc[0][1], A, u23);
                A = bcast2(a01.y); fma2(acc[1][0], A, u01); fma2(acc[1][1], A, u23);
                A = bcast2(a23.x); fma2(acc[2][0], A, u01); fma2(acc[2][1], A, u23);
                A = bcast2(a23.y); fma2(acc[3][0], A, u01); fma2(acc[3][1], A, u23);
            }
            buf ^= 1;
        }
        __syncthreads();  // all compute done; Hs buf0 region reusable as Z

        // dump partial z (both K-halves) to smem
        float* Zk = ks ? Z1 : Z0;
#pragma unroll
        for (int r = 0; r < 4; r++) {
            float2 v0 = unpack2(acc[r][0]);
            float2 v1 = unpack2(acc[r][1]);
            Zk[(r0 + r) * 33 + c0]     = v0.x;
            Zk[(r0 + r) * 33 + c0 + 1] = v0.y;
            Zk[(r0 + r) * 33 + c0 + 2] = v1.x;
            Zk[(r0 + r) * 33 + c0 + 3] = v1.y;
        }
        __syncthreads();

        // gates epilogue (Keras order i,f,g,o); c lives in registers
#pragma unroll
        for (int q = 0; q < 2; q++) {
            int e = tid + q * 256;
            int b = e >> 3, jj = e & 7;
            float zi = Z0[b * 33 + jj]      + Z1[b * 33 + jj]      + xwv[q][0];
            float zf = Z0[b * 33 + 8 + jj]  + Z1[b * 33 + 8 + jj]  + xwv[q][1];
            float zg = Z0[b * 33 + 16 + jj] + Z1[b * 33 + 16 + jj] + xwv[q][2];
            float zo = Z0[b * 33 + 24 + jj] + Z1[b * 33 + 24 + jj] + xwv[q][3];
            float cn = sigf(zf) * c_reg[q] + sigf(zi) * tanhf(zg);
            float hn = sigf(zo) * tanhf(cn);
            c_reg[q] = cn;
            hout[(j0 + jj) * 64 + b] = hn;
            hseq[((size_t)b * Ss + s) * Hh + j0 + jj] = hn;
        }

        // grid barrier among the 64 blocks of this direction
        if (step < Ss - 1) {
            __threadfence();
            __syncthreads();
            if (tid == 0) {
                atomicAdd(&g_cnt[dir], 1u);
                const unsigned target = (unsigned)NBJ * (unsigned)(step + 1);
                unsigned v;
                do {
                    asm volatile("ld.volatile.global.u32 %0, [%1];"
                                 : "=r"(v) : "l"(&g_cnt[dir]));
                } while (v < target);
            }
            __syncthreads();
        }
    }
}

// ---------------------------------------------------------------------------
// Dense + CRF potentials (unchanged)
// ---------------------------------------------------------------------------
__global__ void __launch_bounds__(288) k_dense_crf(
    const float* __restrict__ Wd, const float* __restrict__ bd,
    const float* __restrict__ crf_W, const float* __restrict__ crf_b,
    const float* __restrict__ left_b, const float* __restrict__ right_b)
{
    const int bs = blockIdx.x;
    const int s  = bs & (Ss - 1);

    __shared__ float hsm[2 * Hh];
    __shared__ float lg[Tt];

    const int t = threadIdx.x;
    for (int i = t; i < Hh; i += 288) hsm[i]      = g_hseq[0][(size_t)bs * Hh + i];
    for (int i = t; i < Hh; i += 288) hsm[Hh + i] = g_hseq[1][(size_t)bs * Hh + i];
    __syncthreads();

    const int w = t >> 5, lane = t & 31;
    if (w < Tt) {
        float sum = 0.f;
        for (int k = lane; k < 2 * Hh; k += 32)
            sum += hsm[k] * Wd[k * Tt + w];
#pragma unroll
        for (int off = 16; off; off >>= 1)
            sum += __shfl_xor_sync(0xffffffffu, sum, off);
        if (lane == 0) lg[w] = sum + bd[w];
    }
    __syncthreads();
    if (t < Tt) {
        float p = crf_b[t];
#pragma unroll
        for (int k = 0; k < Tt; k++) p += lg[k] * crf_W[k * Tt + t];
        if (s == 0)      p += left_b[t];
        if (s == Ss - 1) p += right_b[t];
        g_pots[(size_t)bs * Tt + t] = p;
    }
}

// ---------------------------------------------------------------------------
// Viterbi (unchanged)
// ---------------------------------------------------------------------------
__global__ void k_viterbi(const float* __restrict__ trans, float* dec, int as_int)
{
    const int b = blockIdx.x;
    const int t = threadIdx.x;
    if (dec == nullptr) dec = g_dec_dummy;

    __shared__ float alpha[Tt];
    __shared__ float nalpha[Tt];
    __shared__ float tr[Tt * Tt];
    __shared__ short bp[Ss - 1][Tt];

    for (int i = t; i < Tt * Tt; i += 32) tr[i] = trans[i];
    if (t < Tt) alpha[t] = g_pots[((size_t)b * Ss) * Tt + t];
    __syncwarp();

    for (int s = 1; s < Ss; s++) {
        if (t < Tt) {
            float best = alpha[0] + tr[t];
            int arg = 0;
#pragma unroll
            for (int p = 1; p < Tt; p++) {
                float sc = alpha[p] + tr[p * Tt + t];
                if (sc > best) { best = sc; arg = p; }
            }
            nalpha[t] = best + g_pots[((size_t)b * Ss + s) * Tt + t];
            bp[s - 1][t] = (short)arg;
        }
        __syncwarp();
        if (t < Tt) alpha[t] = nalpha[t];
        __syncwarp();
    }

    if (t == 0) {
        int tag = 0; float best = alpha[0];
#pragma unroll
        for (int p = 1; p < Tt; p++)
            if (alpha[p] > best) { best = alpha[p]; tag = p; }
        if (as_int) ((int*)dec)[(size_t)b * Ss + Ss - 1] = tag;
        else        dec[(size_t)b * Ss + Ss - 1] = (float)tag;
        for (int s = Ss - 2; s >= 0; s--) {
            tag = bp[s][tag];
            if (as_int) ((int*)dec)[(size_t)b * Ss + s] = tag;
            else        dec[(size_t)b * Ss + s] = (float)tag;
        }
    }
}

__global__ void k_copy_pots(float* __restrict__ dst) {
    int i = blockIdx.x * 256 + threadIdx.x;
    if (i < Bb * Ss * Tt) dst[i] = g_pots[i];
}

// ---------------------------------------------------------------------------
// Launch
// ---------------------------------------------------------------------------
extern "C" void kernel_launch(void* const* d_in, const int* in_sizes, int n_in,
                              void* d_out, int out_size)
{
    const int*   inputs = (const int*)  d_in[0];
    const float* emb    = (const float*)d_in[1];
    const float* W_fw   = (const float*)d_in[2];
    const float* U_fw   = (const float*)d_in[3];
    const float* b_fw   = (const float*)d_in[4];
    const float* W_bw   = (const float*)d_in[5];
    const float* U_bw   = (const float*)d_in[6];
    const float* b_bw   = (const float*)d_in[7];
    const float* Wd     = (const float*)d_in[8];
    const float* bd     = (const float*)d_in[9];
    const float* crf_W  = (const float*)d_in[10];
    const float* crf_b  = (const float*)d_in[11];
    const float* trans  = (const float*)d_in[12];
    const float* left_b = (const float*)d_in[13];
    const float* right_b= (const float*)d_in[14];

    float* out = (float*)d_out;
    const long long NDEC = (long long)Bb * Ss;        // 32768
    const long long NPOT = (long long)Bb * Ss * Tt;   // 294912

    float* dec_dst = nullptr;
    float* pot_dst = nullptr;
    int as_int = 0;
    if ((long long)out_size >= NDEC + NPOT) {
        dec_dst = out;
        pot_dst = out + NDEC;
    } else if ((long long)out_size == NPOT) {
        pot_dst = out;
    } else {
        dec_dst = out;
        as_int = 1;
    }

    k_zero_state<<<(Hh * Bb + 255) / 256, 256>>>();

    dim3 g1(G4H / 64, (Bb * Ss) / 64, 2);
    k_input_gemm<<<g1, 256>>>(inputs, emb, W_fw, b_fw, W_bw, b_bw);

    const int smem_bytes = (512 * PADU + 2 * 64 * PADH) * (int)sizeof(float); // 104448
    static int smem_set = 0;
    if (!smem_set) {
        cudaFuncSetAttribute(k_lstm_persistent,
                             cudaFuncAttributeMaxDynamicSharedMemorySize, smem_bytes);
        smem_set = 1;
    }
    dim3 g2(NBJ, 2);   // 128 blocks, all resident
    k_lstm_persistent<<<g2, 256, smem_bytes>>>(U_fw, U_bw);

    k_dense_crf<<<Bb * Ss, 288>>>(Wd, bd, crf_W, crf_b, left_b, right_b);

    k_viterbi<<<Bb, 32>>>(trans, dec_dst, as_int);

    if (pot_dst)
        k_copy_pots<<<(Bb * Ss * Tt + 255) / 256, 256>>>(pot_dst);
}

// round 13
// speedup vs baseline: 1.8161x; 1.0020x over previous
#include <cuda_runtime.h>
#include <cuda_bf16.h>
#include <math.h>

// Problem dims
#define Bb  64
#define Ss  512
#define Ee  256
#define Hh  512
#define Tt  9
#define G4H 2048   // 4*H

#define PADU 34    // U smem row pad (floats)
#define PADH 68    // h smem row pad (floats, 16B-aligned rows)
#define NBJ  64    // j-blocks per direction

// ---------------------------------------------------------------------------
// Scratch (device globals; no runtime allocation allowed)
// ---------------------------------------------------------------------------
__device__ float g_xw[2][(size_t)Bb * Ss * G4H];      // input projections per dir
__device__ float g_hseq[2][(size_t)Bb * Ss * Hh];     // h history per dir [b][s][h]
__device__ float g_hstate[2][2][Hh * Bb];             // [dir][parity][j*64 + b]  (transposed!)
__device__ float g_pots[(size_t)Bb * Ss * Tt];
__device__ float g_dec_dummy[Bb * Ss];
__device__ unsigned g_cnt[2];                          // per-dir barrier counters

// ---------------------------------------------------------------------------
// f32x2 helpers
// ---------------------------------------------------------------------------
__device__ __forceinline__ void fma2(unsigned long long& d, unsigned long long a,
                                     unsigned long long b) {
    asm("fma.rn.f32x2 %0, %1, %2, %0;" : "+l"(d) : "l"(a), "l"(b));
}
__device__ __forceinline__ unsigned long long bcast2(float x) {
    unsigned long long r;
    asm("mov.b64 %0, {%1, %1};" : "=l"(r) : "r"(__float_as_uint(x)));
    return r;
}
__device__ __forceinline__ float2 unpack2(unsigned long long v) {
    float2 f;
    asm("mov.b64 {%0, %1}, %2;" : "=f"(f.x), "=f"(f.y) : "l"(v));
    return f;
}
__device__ __forceinline__ float sigf(float x) { return 1.0f / (1.0f + expf(-x)); }

// ---------------------------------------------------------------------------
// Zero state + barrier counters
// ---------------------------------------------------------------------------
__global__ void k_zero_state() {
    int i = blockIdx.x * 256 + threadIdx.x;
    if (i < Hh * Bb) {
        g_hstate[0][0][i] = 0.f; g_hstate[0][1][i] = 0.f;
        g_hstate[1][0][i] = 0.f; g_hstate[1][1][i] = 0.f;
    }
    if (i < 2) g_cnt[i] = 0u;
}

// ---------------------------------------------------------------------------
// Embedding + input projection (unchanged from R11): xw = emb[inputs] @ W + b
// ---------------------------------------------------------------------------
__global__ void __launch_bounds__(256) k_input_gemm(
    const int* __restrict__ inputs, const float* __restrict__ emb,
    const float* __restrict__ W_fw, const float* __restrict__ b_fw,
    const float* __restrict__ W_bw, const float* __restrict__ b_bw)
{
    const int dir = blockIdx.z;
    const float* __restrict__ W    = dir ? W_bw : W_fw;
    const float* __restrict__ bias = dir ? b_bw : b_fw;
    float* __restrict__ out = g_xw[dir];

    const int m0 = blockIdx.y * 64;
    const int n0 = blockIdx.x * 64;

    __shared__ __align__(16) float As[16][65];
    __shared__ __align__(16) float Bs[16][64];
    __shared__ int ridx[64];

    const int t = threadIdx.x;
    if (t < 64) ridx[t] = inputs[m0 + t];
    __syncthreads();

    const int tx = t & 7;
    const int ty = t >> 3;
    const int r0 = ty * 2;
    const int c0 = tx * 8;

    unsigned long long acc[2][4];
#pragma unroll
    for (int r = 0; r < 2; r++)
#pragma unroll
        for (int c = 0; c < 4; c++) acc[r][c] = 0ULL;

    for (int k0 = 0; k0 < Ee; k0 += 16) {
#pragma unroll
        for (int i = 0; i < 4; i++) {
            int li = t + i * 256;
            int m = li >> 4, kk = li & 15;
            As[kk][m] = emb[(size_t)ridx[m] * Ee + k0 + kk];
        }
#pragma unroll
        for (int i = 0; i < 4; i++) {
            int li = t + i * 256;
            int kk = li >> 6, n = li & 63;
            Bs[kk][n] = W[(size_t)(k0 + kk) * G4H + n0 + n];
        }
        __syncthreads();
#pragma unroll
        for (int kk = 0; kk < 16; kk++) {
            unsigned long long a0 = bcast2(As[kk][r0]);
            unsigned long long a1 = bcast2(As[kk][r0 + 1]);
#pragma unroll
            for (int c = 0; c < 4; c++) {
                unsigned long long u2 = *(const unsigned long long*)&Bs[kk][c0 + 2 * c];
                fma2(acc[0][c], a0, u2);
                fma2(acc[1][c], a1, u2);
            }
        }
        __syncthreads();
    }

#pragma unroll
    for (int r = 0; r < 2; r++) {
        int m = m0 + r0 + r;
#pragma unroll
        for (int c = 0; c < 4; c++) {
            float2 v = unpack2(acc[r][c]);
            int n = n0 + c0 + 2 * c;
            v.x += bias[n];
            v.y += bias[n + 1];
            *(float2*)&out[(size_t)m * G4H + n] = v;
        }
    }
}

// ---------------------------------------------------------------------------
// Persistent BiLSTM recurrence. grid=(64,2), 256 threads, all blocks resident.
// Block (dir, jb) owns z columns {gate*512 + jb*8 + jj} and keeps its U slice
// [512][32] in smem for all 512 steps. Software grid barrier per direction.
// h state global layout transposed: hstate[j*64 + b].
// ---------------------------------------------------------------------------
__global__ void __launch_bounds__(256) k_lstm_persistent(
    const float* __restrict__ U_fw, const float* __restrict__ U_bw)
{
    const int dir = blockIdx.y;
    const int jb  = blockIdx.x;
    const int j0  = jb * 8;
    const int tid = threadIdx.x;
    const float* __restrict__ U = dir ? U_bw : U_fw;

    extern __shared__ float sm[];
    float* Us = sm;                       // [512][PADU]
    float* Hs = sm + 512 * PADU;          // [2][64][PADH]
    float* Z0 = Hs;                       // [64][33]  (reuses Hs buf0 between steps)
    float* Z1 = Hs + 64 * 33;

    // ---- stage U slice once: Us[k][c], c = gate*8 + jj ----
    {
        const int c = tid & 31;
        const int gcol = (c >> 3) * Hh + j0 + (c & 7);
        const int kb = tid >> 5;
        for (int i = 0; i < 64; i++) {
            int k = kb + 8 * i;
            Us[k * PADU + c] = U[(size_t)k * G4H + gcol];
        }
    }

    // compute mapping: K-split halves, 4 rows x 4 cols per thread
    const int ks = tid >> 7;              // 0/1
    const int t7 = tid & 127;
    const int r0 = (t7 >> 3) * 4;         // batch rows r0..r0+3
    const int c0 = (t7 & 7) * 4;          // cols c0..c0+3

    // staging mapping
    const int skk = tid >> 4;             // 0..15
    const int sb  = (tid & 15) * 4;       // 0..60

    float c_reg[2] = {0.f, 0.f};
    float* __restrict__ hseq = g_hseq[dir];
    const float* __restrict__ xw = g_xw[dir];

    __syncthreads();

#pragma unroll 1
    for (int step = 0; step < Ss; step++) {
        const int s = dir ? (Ss - 1 - step) : step;
        const float* __restrict__ hin = g_hstate[dir][step & 1];
        float* __restrict__ hout      = g_hstate[dir][(step & 1) ^ 1];

        // prefetch gate biases from xw (used only in epilogue)
        float xwv[2][4];
#pragma unroll
        for (int q = 0; q < 2; q++) {
            int e = tid + q * 256;
            int b = e >> 3, jj = e & 7;
            const float* p = &xw[((size_t)b * Ss + s) * G4H + j0 + jj];
#pragma unroll
            for (int g = 0; g < 4; g++) xwv[q][g] = __ldcs(p + g * Hh);
        }

        unsigned long long acc[4][2];
#pragma unroll
        for (int r = 0; r < 4; r++) { acc[r][0] = 0ULL; acc[r][1] = 0ULL; }

        // prefetch chunk 0 of h (L2-coherent loads; L1 would be stale)
        float4 hv[4];
#pragma unroll
        for (int i = 0; i < 4; i++)
            hv[i] = __ldcg((const float4*)&hin[(skk + 16 * i) * 64 + sb]);

        int buf = 0;
#pragma unroll 1
        for (int ch = 0; ch < 8; ch++) {
            float* hb = Hs + buf * (64 * PADH);
#pragma unroll
            for (int i = 0; i < 4; i++)
                *(float4*)&hb[(skk + 16 * i) * PADH + sb] = hv[i];
            __syncthreads();
            if (ch < 7) {
                int k0n = (ch + 1) * 64;
#pragma unroll
                for (int i = 0; i < 4; i++)
                    hv[i] = __ldcg((const float4*)&hin[(k0n + skk + 16 * i) * 64 + sb]);
            }
            const float* ub  = Us + (ch * 64 + ks * 32) * PADU;
            const float* hbk = hb + (ks * 32) * PADH;
#pragma unroll 16
            for (int kk = 0; kk < 32; kk++) {
                float2 a01 = *(const float2*)&hbk[kk * PADH + r0];
                float2 a23 = *(const float2*)&hbk[kk * PADH + r0 + 2];
                unsigned long long u01 = *(const unsigned long long*)&ub[kk * PADU + c0];
                unsigned long long u23 = *(const unsigned long long*)&ub[kk * PADU + c0 + 2];
                unsigned long long A;
                A = bcast2(a01.x); fma2(acc[0][0], A, u01); fma2(acc[0][1], A, u23);
                A = bcast2(a01.y); fma2(acc[1][0], A, u01); fma2(acc[1][1], A, u23);
                A = bcast2(a23.x); fma2(acc[2][0], A, u01); fma2(acc[2][1], A, u23);
                A = bcast2(a23.y); fma2(acc[3][0], A, u01); fma2(acc[3][1], A, u23);
            }
            buf ^= 1;
        }
        __syncthreads();  // all compute done; Hs buf0 region reusable as Z

        // dump partial z (both K-halves) to smem
        float* Zk = ks ? Z1 : Z0;
#pragma unroll
        for (int r = 0; r < 4; r++) {
            float2 v0 = unpack2(acc[r][0]);
            float2 v1 = unpack2(acc[r][1]);
            Zk[(r0 + r) * 33 + c0]     = v0.x;
            Zk[(r0 + r) * 33 + c0 + 1] = v0.y;
            Zk[(r0 + r) * 33 + c0 + 2] = v1.x;
            Zk[(r0 + r) * 33 + c0 + 3] = v1.y;
        }
        __syncthreads();

        // gates epilogue (Keras order i,f,g,o); c lives in registers
#pragma unroll
        for (int q = 0; q < 2; q++) {
            int e = tid + q * 256;
            int b = e >> 3, jj = e & 7;
            float zi = Z0[b * 33 + jj]      + Z1[b * 33 + jj]      + xwv[q][0];
            float zf = Z0[b * 33 + 8 + jj]  + Z1[b * 33 + 8 + jj]  + xwv[q][1];
            float zg = Z0[b * 33 + 16 + jj] + Z1[b * 33 + 16 + jj] + xwv[q][2];
            float zo = Z0[b * 33 + 24 + jj] + Z1[b * 33 + 24 + jj] + xwv[q][3];
            float cn = sigf(zf) * c_reg[q] + sigf(zi) * tanhf(zg);
            float hn = sigf(zo) * tanhf(cn);
            c_reg[q] = cn;
            hout[(j0 + jj) * 64 + b] = hn;
            hseq[((size_t)b * Ss + s) * Hh + j0 + jj] = hn;
        }

        // grid barrier among the 64 blocks of this direction
        if (step < Ss - 1) {
            __threadfence();
            __syncthreads();
            if (tid == 0) {
                atomicAdd(&g_cnt[dir], 1u);
                const unsigned target = (unsigned)NBJ * (unsigned)(step + 1);
                unsigned v;
                do {
                    asm volatile("ld.volatile.global.u32 %0, [%1];"
                                 : "=r"(v) : "l"(&g_cnt[dir]));
                } while (v < target);
            }
            __syncthreads();
        }
    }
}

// ---------------------------------------------------------------------------
// Dense + CRF potentials (unchanged)
// ---------------------------------------------------------------------------
__global__ void __launch_bounds__(288) k_dense_crf(
    const float* __restrict__ Wd, const float* __restrict__ bd,
    const float* __restrict__ crf_W, const float* __restrict__ crf_b,
    const float* __restrict__ left_b, const float* __restrict__ right_b)
{
    const int bs = blockIdx.x;
    const int s  = bs & (Ss - 1);

    __shared__ float hsm[2 * Hh];
    __shared__ float lg[Tt];

    const int t = threadIdx.x;
    for (int i = t; i < Hh; i += 288) hsm[i]      = g_hseq[0][(size_t)bs * Hh + i];
    for (int i = t; i < Hh; i += 288) hsm[Hh + i] = g_hseq[1][(size_t)bs * Hh + i];
    __syncthreads();

    const int w = t >> 5, lane = t & 31;
    if (w < Tt) {
        float sum = 0.f;
        for (int k = lane; k < 2 * Hh; k += 32)
            sum += hsm[k] * Wd[k * Tt + w];
#pragma unroll
        for (int off = 16; off; off >>= 1)
            sum += __shfl_xor_sync(0xffffffffu, sum, off);
        if (lane == 0) lg[w] = sum + bd[w];
    }
    __syncthreads();
    if (t < Tt) {
        float p = crf_b[t];
#pragma unroll
        for (int k = 0; k < Tt; k++) p += lg[k] * crf_W[k * Tt + t];
        if (s == 0)      p += left_b[t];
        if (s == Ss - 1) p += right_b[t];
        g_pots[(size_t)bs * Tt + t] = p;
    }
}

// ---------------------------------------------------------------------------
// Viterbi (unchanged)
// ---------------------------------------------------------------------------
__global__ void k_viterbi(const float* __restrict__ trans, float* dec, int as_int)
{
    const int b = blockIdx.x;
    const int t = threadIdx.x;
    if (dec == nullptr) dec = g_dec_dummy;

    __shared__ float alpha[Tt];
    __shared__ float nalpha[Tt];
    __shared__ float tr[Tt * Tt];
    __shared__ short bp[Ss - 1][Tt];

    for (int i = t; i < Tt * Tt; i += 32) tr[i] = trans[i];
    if (t < Tt) alpha[t] = g_pots[((size_t)b * Ss) * Tt + t];
    __syncwarp();

    for (int s = 1; s < Ss; s++) {
        if (t < Tt) {
            float best = alpha[0] + tr[t];
            int arg = 0;
#pragma unroll
            for (int p = 1; p < Tt; p++) {
                float sc = alpha[p] + tr[p * Tt + t];
                if (sc > best) { best = sc; arg = p; }
            }
            nalpha[t] = best + g_pots[((size_t)b * Ss + s) * Tt + t];
            bp[s - 1][t] = (short)arg;
        }
        __syncwarp();
        if (t < Tt) alpha[t] = nalpha[t];
        __syncwarp();
    }

    if (t == 0) {
        int tag = 0; float best = alpha[0];
#pragma unroll
        for (int p = 1; p < Tt; p++)
            if (alpha[p] > best) { best = alpha[p]; tag = p; }
        if (as_int) ((int*)dec)[(size_t)b * Ss + Ss - 1] = tag;
        else        dec[(size_t)b * Ss + Ss - 1] = (float)tag;
        for (int s = Ss - 2; s >= 0; s--) {
            tag = bp[s][tag];
            if (as_int) ((int*)dec)[(size_t)b * Ss + s] = tag;
            else        dec[(size_t)b * Ss + s] = (float)tag;
        }
    }
}

__global__ void k_copy_pots(float* __restrict__ dst) {
    int i = blockIdx.x * 256 + threadIdx.x;
    if (i < Bb * Ss * Tt) dst[i] = g_pots[i];
}

// ---------------------------------------------------------------------------
// Launch
// ---------------------------------------------------------------------------
extern "C" void kernel_launch(void* const* d_in, const int* in_sizes, int n_in,
                              void* d_out, int out_size)
{
    const int*   inputs = (const int*)  d_in[0];
    const float* emb    = (const float*)d_in[1];
    const float* W_fw   = (const float*)d_in[2];
    const float* U_fw   = (const float*)d_in[3];
    const float* b_fw   = (const float*)d_in[4];
    const float* W_bw   = (const float*)d_in[5];
    const float* U_bw   = (const float*)d_in[6];
    const float* b_bw   = (const float*)d_in[7];
    const float* Wd     = (const float*)d_in[8];
    const float* bd     = (const float*)d_in[9];
    const float* crf_W  = (const float*)d_in[10];
    const float* crf_b  = (const float*)d_in[11];
    const float* trans  = (const float*)d_in[12];
    const float* left_b = (const float*)d_in[13];
    const float* right_b= (const float*)d_in[14];

    float* out = (float*)d_out;
    const long long NDEC = (long long)Bb * Ss;        // 32768
    const long long NPOT = (long long)Bb * Ss * Tt;   // 294912

    float* dec_dst = nullptr;
    float* pot_dst = nullptr;
    int as_int = 0;
    if ((long long)out_size >= NDEC + NPOT) {
        dec_dst = out;
        pot_dst = out + NDEC;
    } else if ((long long)out_size == NPOT) {
        pot_dst = out;
    } else {
        dec_dst = out;
        as_int = 1;
    }

    k_zero_state<<<(Hh * Bb + 255) / 256, 256>>>();

    dim3 g1(G4H / 64, (Bb * Ss) / 64, 2);
    k_input_gemm<<<g1, 256>>>(inputs, emb, W_fw, b_fw, W_bw, b_bw);

    const int smem_bytes = (512 * PADU + 2 * 64 * PADH) * (int)sizeof(float); // 104448
    static int smem_set = 0;
    if (!smem_set) {
        cudaFuncSetAttribute(k_lstm_persistent,
                             cudaFuncAttributeMaxDynamicSharedMemorySize, smem_bytes);
        smem_set = 1;
    }
    dim3 g2(NBJ, 2);   // 128 blocks, all resident
    k_lstm_persistent<<<g2, 256, smem_bytes>>>(U_fw, U_bw);

    k_dense_crf<<<Bb * Ss, 288>>>(Wd, bd, crf_W, crf_b, left_b, right_b);

    k_viterbi<<<Bb, 32>>>(trans, dec_dst, as_int);

    if (pot_dst)
        k_copy_pots<<<(Bb * Ss * Tt + 255) / 256, 256>>>(pot_dst);
}